// round 1
// baseline (speedup 1.0000x reference)
#include <cuda_runtime.h>

#define DD  1024
#define BB  128
#define LLn 196
#define LP1 197

// ---------------- scratch (no allocs allowed) ----------------
__device__ float g_fr [BB*DD];
__device__ float g_fre[BB*DD];
__device__ float g_ho [BB*DD];
__device__ float g_hoe[BB*DD];
__device__ float g_att[BB*DD];
__device__ float g_scores[BB*LP1];
__device__ float g_pi[BB*LP1];

// ---------------- f32x2 helpers ----------------
__device__ __forceinline__ unsigned long long fma2(unsigned long long a,
                                                   unsigned long long b,
                                                   unsigned long long c) {
    unsigned long long r;
    asm("fma.rn.f32x2 %0, %1, %2, %3;" : "=l"(r) : "l"(a), "l"(b), "l"(c));
    return r;
}
__device__ __forceinline__ unsigned long long dup2(float x) {
    unsigned long long r;
    asm("mov.b64 %0, {%1, %1};" : "=l"(r) : "f"(x));
    return r;
}
__device__ __forceinline__ float tanh_fast(float x) {
    float y;
    asm("tanh.approx.f32 %0, %1;" : "=f"(y) : "f"(x));
    return y;
}

// ---------------- GEMM: C[128,1024] = act(A[128,1024] @ W[1024,1024]^T + b) ----------------
// BM=32, BN=64, BK=16, 128 threads, thread tile 4m x 4n (m-paired f32x2 accum).
// grid = (16, 4, z) ; z selects problem 0/1 (two independent GEMMs per launch).
__global__ void __launch_bounds__(128)
gemm_kernel(const float* __restrict__ A0, const float* __restrict__ W0,
            const float* __restrict__ bias0, float* __restrict__ C0, int act0,
            const float* __restrict__ A1, const float* __restrict__ W1,
            const float* __restrict__ bias1, float* __restrict__ C1, int act1)
{
    const float* A  = A0;  const float* W = W0;  const float* bias = bias0;
    float* C = C0;  int act = act0;
    if (blockIdx.z == 1) { A = A1; W = W1; bias = bias1; C = C1; act = act1; }

    __shared__ float As[2][16][32];
    __shared__ float Bs[2][16][64];

    const int t  = threadIdx.x;
    const int bm = blockIdx.y << 5;
    const int bn = blockIdx.x << 6;

    const int ar = t >> 2, ac = (t & 3) << 2;   // A tile loader: row 0..31, k 0/4/8/12
    const int br = t >> 1, bc = (t & 1) << 3;   // W tile loader: row 0..63, k 0/8
    const int tx = t & 15, ty = t >> 4;
    const int m0 = ty << 2, n0 = tx << 2;

    const float* Ap = A + (size_t)(bm + ar) * DD + ac;
    const float* Wp = W + (size_t)(bn + br) * DD + bc;

    unsigned long long acc01[4], acc23[4];
#pragma unroll
    for (int j = 0; j < 4; j++) { acc01[j] = 0ull; acc23[j] = 0ull; }

    float4 av  = *(const float4*)Ap;
    float4 bv0 = *(const float4*)Wp;
    float4 bv1 = *(const float4*)(Wp + 4);

    As[0][ac+0][ar] = av.x;  As[0][ac+1][ar] = av.y;
    As[0][ac+2][ar] = av.z;  As[0][ac+3][ar] = av.w;
    Bs[0][bc+0][br] = bv0.x; Bs[0][bc+1][br] = bv0.y;
    Bs[0][bc+2][br] = bv0.z; Bs[0][bc+3][br] = bv0.w;
    Bs[0][bc+4][br] = bv1.x; Bs[0][bc+5][br] = bv1.y;
    Bs[0][bc+6][br] = bv1.z; Bs[0][bc+7][br] = bv1.w;
    __syncthreads();

    int buf = 0;
#pragma unroll 1
    for (int kb = 0; kb < 64; kb++) {
        if (kb < 63) {
            av  = *(const float4*)(Ap + (kb + 1) * 16);
            bv0 = *(const float4*)(Wp + (kb + 1) * 16);
            bv1 = *(const float4*)(Wp + (kb + 1) * 16 + 4);
        }
#pragma unroll
        for (int k = 0; k < 16; k++) {
            union { float4 v; unsigned long long u[2]; } au;
            au.v = *(const float4*)&As[buf][k][m0];
            float4 bv = *(const float4*)&Bs[buf][k][n0];
            unsigned long long b0 = dup2(bv.x), b1 = dup2(bv.y),
                               b2 = dup2(bv.z), b3 = dup2(bv.w);
            acc01[0] = fma2(au.u[0], b0, acc01[0]);
            acc01[1] = fma2(au.u[0], b1, acc01[1]);
            acc01[2] = fma2(au.u[0], b2, acc01[2]);
            acc01[3] = fma2(au.u[0], b3, acc01[3]);
            acc23[0] = fma2(au.u[1], b0, acc23[0]);
            acc23[1] = fma2(au.u[1], b1, acc23[1]);
            acc23[2] = fma2(au.u[1], b2, acc23[2]);
            acc23[3] = fma2(au.u[1], b3, acc23[3]);
        }
        if (kb < 63) {
            const int nb = buf ^ 1;
            As[nb][ac+0][ar] = av.x;  As[nb][ac+1][ar] = av.y;
            As[nb][ac+2][ar] = av.z;  As[nb][ac+3][ar] = av.w;
            Bs[nb][bc+0][br] = bv0.x; Bs[nb][bc+1][br] = bv0.y;
            Bs[nb][bc+2][br] = bv0.z; Bs[nb][bc+3][br] = bv0.w;
            Bs[nb][bc+4][br] = bv1.x; Bs[nb][bc+5][br] = bv1.y;
            Bs[nb][bc+6][br] = bv1.z; Bs[nb][bc+7][br] = bv1.w;
            __syncthreads();
            buf = nb;
        }
    }

    const float4 bi = *(const float4*)&bias[bn + n0];
    const float bif[4] = { bi.x, bi.y, bi.z, bi.w };
#pragma unroll
    for (int i = 0; i < 4; i++) {
        float o[4];
#pragma unroll
        for (int j = 0; j < 4; j++) {
            union { unsigned long long u; float f[2]; } u;
            u.u = (i < 2) ? acc01[j] : acc23[j];
            o[j] = u.f[i & 1] + bif[j];
        }
        if (act == 1) {
#pragma unroll
            for (int j = 0; j < 4; j++) o[j] = fmaxf(o[j], 0.0f);
        } else if (act == 2) {
#pragma unroll
            for (int j = 0; j < 4; j++) o[j] = tanhf(o[j]);
        }
        float4 ov; ov.x = o[0]; ov.y = o[1]; ov.z = o[2]; ov.w = o[3];
        *(float4*)&C[(size_t)(bm + m0 + i) * DD + bn + n0] = ov;
    }
}

// ---------------- scores[b,l] = Wa . tanh(E[b,l,:] + hoe[b,:]) + ba ----------------
__global__ void __launch_bounds__(128)
scores_kernel(const float* __restrict__ embed,
              const float* __restrict__ Wa, const float* __restrict__ ba)
{
    const int l = blockIdx.x, b = blockIdx.y, t = threadIdx.x;
    const float* row  = (l == 0) ? (g_fre + (size_t)b * DD)
                                 : (embed + ((size_t)b * LLn + (l - 1)) * DD);
    const float* hrow = g_hoe + (size_t)b * DD;
    const int d0 = t << 3;

    float s = 0.0f;
#pragma unroll
    for (int c = 0; c < 2; c++) {
        float4 e = *(const float4*)(row  + d0 + c * 4);
        float4 h = *(const float4*)(hrow + d0 + c * 4);
        float4 w = *(const float4*)(Wa   + d0 + c * 4);
        s += tanh_fast(e.x + h.x) * w.x + tanh_fast(e.y + h.y) * w.y
           + tanh_fast(e.z + h.z) * w.z + tanh_fast(e.w + h.w) * w.w;
    }
#pragma unroll
    for (int o = 16; o; o >>= 1) s += __shfl_xor_sync(0xffffffffu, s, o);

    __shared__ float red[4];
    if ((t & 31) == 0) red[t >> 5] = s;
    __syncthreads();
    if (t == 0)
        g_scores[b * LP1 + l] = red[0] + red[1] + red[2] + red[3] + ba[0];
}

// ---------------- softmax over L+1=197 per batch row ----------------
__global__ void __launch_bounds__(256)
softmax_kernel()
{
    const int b = blockIdx.x, t = threadIdx.x;
    __shared__ float red[8];

    float v = (t < LP1) ? g_scores[b * LP1 + t] : -3.4e38f;
    float m = v;
#pragma unroll
    for (int o = 16; o; o >>= 1) m = fmaxf(m, __shfl_xor_sync(0xffffffffu, m, o));
    if ((t & 31) == 0) red[t >> 5] = m;
    __syncthreads();
    float mx = red[0];
#pragma unroll
    for (int i = 1; i < 8; i++) mx = fmaxf(mx, red[i]);
    __syncthreads();

    float e = (t < LP1) ? expf(v - mx) : 0.0f;
    float s = e;
#pragma unroll
    for (int o = 16; o; o >>= 1) s += __shfl_xor_sync(0xffffffffu, s, o);
    if ((t & 31) == 0) red[t >> 5] = s;
    __syncthreads();
    float tot = red[0] + red[1] + red[2] + red[3]
              + red[4] + red[5] + red[6] + red[7];
    if (t < LP1) g_pi[b * LP1 + t] = e / tot;
}

// ---------------- att[b,:] = PI[b,0]*fr + sum_l PI[b,l+1]*conv[b,l,:] + ho[b,:] ----------------
__global__ void __launch_bounds__(256)
wsum_kernel(const float* __restrict__ conv)
{
    const int b = blockIdx.x, t = threadIdx.x;
    __shared__ float sp[LP1];
    if (t < LP1) sp[t] = g_pi[b * LP1 + t];
    __syncthreads();

    const int d0 = t << 2;
    float4 acc;
    {
        float4 f = *(const float4*)(g_fr + (size_t)b * DD + d0);
        float p = sp[0];
        acc.x = f.x * p; acc.y = f.y * p; acc.z = f.z * p; acc.w = f.w * p;
    }
    const float* base = conv + (size_t)b * LLn * DD + d0;
#pragma unroll 1
    for (int l = 0; l < LLn; l += 4) {
        float4 v0 = *(const float4*)(base + (size_t)(l + 0) * DD);
        float4 v1 = *(const float4*)(base + (size_t)(l + 1) * DD);
        float4 v2 = *(const float4*)(base + (size_t)(l + 2) * DD);
        float4 v3 = *(const float4*)(base + (size_t)(l + 3) * DD);
        float p0 = sp[l + 1], p1 = sp[l + 2], p2 = sp[l + 3], p3 = sp[l + 4];
        acc.x += v0.x * p0; acc.y += v0.y * p0; acc.z += v0.z * p0; acc.w += v0.w * p0;
        acc.x += v1.x * p1; acc.y += v1.y * p1; acc.z += v1.z * p1; acc.w += v1.w * p1;
        acc.x += v2.x * p2; acc.y += v2.y * p2; acc.z += v2.z * p2; acc.w += v2.w * p2;
        acc.x += v3.x * p3; acc.y += v3.y * p3; acc.z += v3.z * p3; acc.w += v3.w * p3;
    }
    float4 h = *(const float4*)(g_ho + (size_t)b * DD + d0);
    acc.x += h.x; acc.y += h.y; acc.z += h.z; acc.w += h.w;
    *(float4*)(g_att + (size_t)b * DD + d0) = acc;
}

// ---------------- host launcher ----------------
extern "C" void kernel_launch(void* const* d_in, const int* in_sizes, int n_in,
                              void* d_out, int out_size)
{
    (void)in_sizes; (void)n_in; (void)out_size;
    const float* h_out = (const float*)d_in[0];
    const float* fake  = (const float*)d_in[1];
    const float* conv  = (const float*)d_in[2];
    const float* embed = (const float*)d_in[3];
    const float* W_fr  = (const float*)d_in[4];
    const float* b_fr  = (const float*)d_in[5];
    const float* W_fre = (const float*)d_in[6];
    const float* b_fre = (const float*)d_in[7];
    const float* W_ho  = (const float*)d_in[8];
    const float* b_ho  = (const float*)d_in[9];
    const float* W_hoe = (const float*)d_in[10];
    const float* b_hoe = (const float*)d_in[11];
    const float* W_a   = (const float*)d_in[12];
    const float* b_a   = (const float*)d_in[13];
    const float* W_h   = (const float*)d_in[14];
    const float* b_h   = (const float*)d_in[15];

    float *fr, *fre, *ho, *hoe, *att;
    cudaGetSymbolAddress((void**)&fr,  g_fr);
    cudaGetSymbolAddress((void**)&fre, g_fre);
    cudaGetSymbolAddress((void**)&ho,  g_ho);
    cudaGetSymbolAddress((void**)&hoe, g_hoe);
    cudaGetSymbolAddress((void**)&att, g_att);

    dim3 gb(128);
    // fr = relu(fake @ W_fr^T + b), ho = tanh(h_out @ W_ho^T + b)
    gemm_kernel<<<dim3(16, 4, 2), gb>>>(fake, W_fr, b_fr, fr, 1,
                                        h_out, W_ho, b_ho, ho, 2);
    // fr_e = fr @ W_fre^T + b, ho_e = ho @ W_hoe^T + b
    gemm_kernel<<<dim3(16, 4, 2), gb>>>(fr, W_fre, b_fre, fre, 0,
                                        ho, W_hoe, b_hoe, hoe, 0);
    scores_kernel<<<dim3(LP1, BB), 128>>>(embed, W_a, b_a);
    softmax_kernel<<<BB, 256>>>();
    wsum_kernel<<<BB, 256>>>(conv);
    // h = tanh(att @ W_h^T + b_h)
    gemm_kernel<<<dim3(16, 4, 1), gb>>>(att, W_h, b_h, (float*)d_out, 2,
                                        att, W_h, b_h, (float*)d_out, 2);
}